// round 6
// baseline (speedup 1.0000x reference)
#include <cuda_runtime.h>
#include <float.h>

// features: [B=8, X=128, Y=128, C=128] f32   (C contiguous)
// rois:     [B, N=128, 4] i32  (minX, minY, maxX, maxY)
// out:      [B, N, 7, 7, C] f32
// out[b,n,h,w,c] = max over x in xbin(w), y in ybin(h) of features[b,x,y,c]
//
// Generator guarantees ROI side >= 2*pool -> dx,dy >= 2, every bin >= 2x2.
// Max is idempotent: odd tails are covered by SHIFTED pairs (overlap inside
// the bin), so the hot loop has no scalar remainders and no clamps.

#define PH 7
#define PW 7
#define B_ 8
#define N_ 128
#define XDIM 128
#define YDIM 128
#define CDIM 128
#define C4   (CDIM / 4)          // 32 float4 per pixel
#define COLS (YDIM * C4)         // float4 stride for +1 in x (4096)

__device__ __forceinline__ float4 f4max(float4 a, float4 b) {
    return make_float4(fmaxf(a.x, b.x), fmaxf(a.y, b.y),
                       fmaxf(a.z, b.z), fmaxf(a.w, b.w));
}

// Reduce one pair of adjacent x-columns over rows [0, ny) (plus shifted tail).
__device__ __forceinline__ void col_pair(const float4* __restrict__ p0,
                                         int ny,
                                         float4& m0, float4& m1,
                                         float4& m2, float4& m3)
{
    const float4* p1 = p0 + COLS;
    int i = 0;
    // steady state: 8 independent LDG.128 per iteration
    for (; i + 4 <= ny; i += 4) {
        float4 a0 = p0[(i + 0) * C4];
        float4 a1 = p0[(i + 1) * C4];
        float4 a2 = p0[(i + 2) * C4];
        float4 a3 = p0[(i + 3) * C4];
        float4 b0 = p1[(i + 0) * C4];
        float4 b1 = p1[(i + 1) * C4];
        float4 b2 = p1[(i + 2) * C4];
        float4 b3 = p1[(i + 3) * C4];
        m0 = f4max(m0, f4max(a0, a2));
        m1 = f4max(m1, f4max(a1, a3));
        m2 = f4max(m2, f4max(b0, b2));
        m3 = f4max(m3, f4max(b1, b3));
    }
    if (i + 2 <= ny) {           // one full row-pair
        float4 a0 = p0[(i + 0) * C4];
        float4 a1 = p0[(i + 1) * C4];
        float4 b0 = p1[(i + 0) * C4];
        float4 b1 = p1[(i + 1) * C4];
        m0 = f4max(m0, a0);
        m1 = f4max(m1, a1);
        m2 = f4max(m2, b0);
        m3 = f4max(m3, b1);
    }
    if (ny & 1) {                // shifted row-pair covering rows ny-2, ny-1
        float4 a0 = p0[(ny - 2) * C4];
        float4 a1 = p0[(ny - 1) * C4];
        float4 b0 = p1[(ny - 2) * C4];
        float4 b1 = p1[(ny - 1) * C4];
        m0 = f4max(m0, a0);
        m1 = f4max(m1, a1);
        m2 = f4max(m2, b0);
        m3 = f4max(m3, b1);
    }
}

__global__ __launch_bounds__(PW * 32, 6)
void roi_maxpool_kernel(const float4* __restrict__ features,
                        const int4*   __restrict__ rois,
                        float4*       __restrict__ out)
{
    // one block per (b, n, h); one warp per w-bin
    int bid  = blockIdx.x;
    int h    = bid % PH;
    int t    = bid / PH;          // t = b*N_ + n
    int b    = t >> 7;            // / N_
    int w    = threadIdx.x >> 5;
    int lane = threadIdx.x & 31;

    const int4 r = rois[t];
    int minX = r.x, minY = r.y, maxX = r.z, maxY = r.w;

    int dx = (maxX - minX) / PW;
    int dy = (maxY - minY) / PH;

    int y0 = minY + h * dy;
    int ny = (h == PH - 1) ? (maxY - y0) : dy;   // >= 2
    int x0 = minX + w * dx;
    int nx = (w == PW - 1) ? (maxX - x0) : dx;   // >= 2

    const float4 NEG = make_float4(-FLT_MAX, -FLT_MAX, -FLT_MAX, -FLT_MAX);
    float4 m0 = NEG, m1 = NEG, m2 = NEG, m3 = NEG;

    // 32-bit indexing: max index 8*128*128*32 = 4.19M < 2^31
    const float4* base = features + (b * XDIM * COLS) + x0 * COLS + y0 * C4 + lane;

    int nxp = nx >> 1;
    for (int j = 0; j < nxp; ++j)
        col_pair(base + (2 * j) * COLS, ny, m0, m1, m2, m3);
    if (nx & 1)                   // shifted column-pair covering cols nx-2, nx-1
        col_pair(base + (nx - 2) * COLS, ny, m0, m1, m2, m3);

    float4 m = f4max(f4max(m0, m1), f4max(m2, m3));

    // output index: (bid*PW + w)*C4 + lane   (bid = t*PH + h)
    out[(bid * PW + w) * C4 + lane] = m;
}

extern "C" void kernel_launch(void* const* d_in, const int* in_sizes, int n_in,
                              void* d_out, int out_size)
{
    const float4* features = (const float4*)d_in[0];
    const int4*   rois     = (const int4*)d_in[1];
    float4*       out      = (float4*)d_out;

    dim3 grid(B_ * N_ * PH);     // 7168
    dim3 block(PW * 32);         // 224
    roi_maxpool_kernel<<<grid, block>>>(features, rois, out);
}

// round 7
// speedup vs baseline: 1.3695x; 1.3695x over previous
#include <cuda_runtime.h>
#include <float.h>

// features: [B=8, X=128, Y=128, C=128] f32   (C contiguous)
// rois:     [B, N=128, 4] i32  (minX, minY, maxX, maxY)
// out:      [B, N, 7, 7, C] f32
//
// Two-pass pyramid:
//   Pass 1: P1[b][x][y][c] = max(f[x..x+1][y..y+1])   (sliding 2x2 max)
//           valid for x<=126, y<=126 (stored full-size in scratch)
//   Pass 2: each bin (>=2x2 guaranteed) = max over P1 sampled at stride 2,
//           positions clamped to bin_end-2 (overlap is legal for max).

#define PH 7
#define PW 7
#define B_ 8
#define N_ 128
#define XDIM 128
#define YDIM 128
#define C4   32                  // 32 float4 per pixel (C=128)
#define COLS (YDIM * C4)         // float4 stride for +1 in x (4096)

// 64 MB scratch: [b][x][y][c4] float4
__device__ float4 d_P1[B_ * XDIM * YDIM * C4];

__device__ __forceinline__ float4 f4max(float4 a, float4 b) {
    return make_float4(fmaxf(a.x, b.x), fmaxf(a.y, b.y),
                       fmaxf(a.z, b.z), fmaxf(a.w, b.w));
}

// ---------------- Pass 1: build sliding 2x2 max ----------------
// warp -> (b, x, ychunk). 8 chunks of 16 rows. x in [0,127). Register-carried
// row pair: each element of rows x, x+1 loaded once per warp.
#define P1_WPB 8
#define P1_CHUNKS 8
#define P1_ROWS 16
#define P1_WARPS (B_ * (XDIM - 1) * P1_CHUNKS)   // 8*127*8 = 8128

__global__ __launch_bounds__(P1_WPB * 32)
void build_p1_kernel(const float4* __restrict__ f)
{
    int gw   = blockIdx.x * P1_WPB + (threadIdx.x >> 5);
    if (gw >= P1_WARPS) return;
    int lane = threadIdx.x & 31;

    int chunk = gw & (P1_CHUNKS - 1);
    int t     = gw >> 3;
    int x     = t % (XDIM - 1);
    int b     = t / (XDIM - 1);
    int y0    = chunk * P1_ROWS;

    const float4* p0 = f + (b * XDIM + x) * COLS + y0 * C4 + lane;
    float4* o = d_P1 + (b * XDIM + x) * COLS + y0 * C4 + lane;

    int maxoff = (127 - y0) * C4;   // clamp load offset to y=127

    float4 pa = p0[0];
    float4 pb = p0[COLS];

    #pragma unroll 4
    for (int i = 0; i < P1_ROWS; ++i) {
        int off = min((i + 1) * C4, maxoff);
        float4 a  = p0[off];
        float4 bb = p0[COLS + off];
        float4 r  = f4max(f4max(pa, a), f4max(pb, bb));
        o[i * C4] = r;              // y=127 store (chunk 7, i=15) is unused scratch
        pa = a;
        pb = bb;
    }
}

// ---------------- Pass 2: ROI pooling from P1 ----------------
// block per (b, n, h); warp per w-bin. Bin [x0,x1)x[y0,y1), nx,ny >= 2.
// Sample P1 at x0+2k clamped to x1-2 (cx = ceil(nx/2)); same in y.
__global__ __launch_bounds__(PW * 32)
void roi_pool_p1_kernel(const int4* __restrict__ rois,
                        float4*     __restrict__ out)
{
    int bid  = blockIdx.x;
    int h    = bid % PH;
    int t    = bid / PH;          // t = b*N_ + n
    int b    = t >> 7;            // / N_
    int w    = threadIdx.x >> 5;
    int lane = threadIdx.x & 31;

    const int4 r = rois[t];
    int dx = (r.z - r.x) / PW;
    int dy = (r.w - r.y) / PH;

    int y0 = r.y + h * dy;
    int ny = (h == PH - 1) ? (r.w - y0) : dy;    // >= 2
    int x0 = r.x + w * dx;
    int nx = (w == PW - 1) ? (r.z - x0) : dx;    // >= 2

    int cx = (nx + 1) >> 1;
    int cy = (ny + 1) >> 1;
    int xle = (nx - 2) * COLS;    // clamp: last x sample = x1-2
    int yle = (ny - 2) * C4;      // clamp: last y sample = y1-2

    const float4* base = d_P1 + (b * XDIM + x0) * COLS + y0 * C4 + lane;

    const float4 NEG = make_float4(-FLT_MAX, -FLT_MAX, -FLT_MAX, -FLT_MAX);
    float4 m0 = NEG, m1 = NEG, m2 = NEG, m3 = NEG;

    int j = 0;
    for (; j + 2 <= cx; j += 2) {                 // two sample-columns at once
        const float4* pA = base + min(2 * j * COLS, xle);
        const float4* pB = base + min((2 * j + 2) * COLS, xle);
        int i = 0;
        for (; i + 2 <= cy; i += 2) {
            float4 a0 = pA[min(2 * i * C4, yle)];
            float4 a1 = pA[min((2 * i + 2) * C4, yle)];
            float4 b0 = pB[min(2 * i * C4, yle)];
            float4 b1 = pB[min((2 * i + 2) * C4, yle)];
            m0 = f4max(m0, a0);
            m1 = f4max(m1, a1);
            m2 = f4max(m2, b0);
            m3 = f4max(m3, b1);
        }
        if (i < cy) {
            int yo = min(2 * i * C4, yle);
            m0 = f4max(m0, pA[yo]);
            m2 = f4max(m2, pB[yo]);
        }
    }
    if (j < cx) {                                  // last single sample-column
        const float4* pA = base + min(2 * j * COLS, xle);
        int i = 0;
        for (; i + 2 <= cy; i += 2) {
            float4 a0 = pA[min(2 * i * C4, yle)];
            float4 a1 = pA[min((2 * i + 2) * C4, yle)];
            m0 = f4max(m0, a0);
            m1 = f4max(m1, a1);
        }
        if (i < cy) {
            m0 = f4max(m0, pA[min(2 * i * C4, yle)]);
        }
    }

    float4 m = f4max(f4max(m0, m1), f4max(m2, m3));
    out[(bid * PW + w) * C4 + lane] = m;           // bid = t*PH + h
}

extern "C" void kernel_launch(void* const* d_in, const int* in_sizes, int n_in,
                              void* d_out, int out_size)
{
    const float4* features = (const float4*)d_in[0];
    const int4*   rois     = (const int4*)d_in[1];
    float4*       out      = (float4*)d_out;

    dim3 grid1((P1_WARPS + P1_WPB - 1) / P1_WPB);  // 1016 blocks
    dim3 block1(P1_WPB * 32);                      // 256
    build_p1_kernel<<<grid1, block1>>>(features);

    dim3 grid2(B_ * N_ * PH);                      // 7168
    dim3 block2(PW * 32);                          // 224
    roi_pool_p1_kernel<<<grid2, block2>>>(rois, out);
}